// round 1
// baseline (speedup 1.0000x reference)
#include <cuda_runtime.h>
#include <cuda_bf16.h>

#define SDIM 2048
#define BDIM 4
#define HDIM 1024
#define MPROJ (SDIM * BDIM)   // 8192

// Scratch (device globals: allocation-free, graph-capturable)
__device__ float g_Q[(size_t)BDIM * SDIM * HDIM];   // 32 MB  [B][S][H]
__device__ float g_K[(size_t)BDIM * SDIM * HDIM];   // 32 MB  [B][S][H]
__device__ float g_V[(size_t)BDIM * SDIM * HDIM];   // 32 MB  [B][S][H]
__device__ float g_SC[(size_t)BDIM * SDIM * SDIM];  // 64 MB  [B][S][S]

// ---------------------------------------------------------------------------
// GEMM skeleton: 128x128 tile, BK=8, 256 threads, 8x8 accum per thread.
// NT variant: both A and B are K-contiguous (row-major [rows][K]).
// ---------------------------------------------------------------------------

// Q/K/V projection: C[m][n] = sum_h x[m][h] * W[n][h] + bias[n]
// x is [S,B,H] flattened to [M=8192][K=1024] with m = s*B + b.
// Output scattered to [B][S][H].
__global__ void __launch_bounds__(256) proj_kernel(
    const float* __restrict__ x,
    const float* __restrict__ Wq, const float* __restrict__ bq,
    const float* __restrict__ Wk, const float* __restrict__ bk,
    const float* __restrict__ Wv, const float* __restrict__ bv)
{
    const float* W; const float* bias; float* out;
    if (blockIdx.z == 0)      { W = Wq; bias = bq; out = g_Q; }
    else if (blockIdx.z == 1) { W = Wk; bias = bk; out = g_K; }
    else                      { W = Wv; bias = bv; out = g_V; }

    __shared__ float As[8][132];
    __shared__ float Bs[8][132];

    const int t    = threadIdx.x;
    const int m0   = blockIdx.y * 128;
    const int n0   = blockIdx.x * 128;
    const int lrow = t >> 1;            // 0..127
    const int lk4  = (t & 1) * 4;       // 0 or 4
    const int ty   = t >> 4;            // 0..15 (m sub-tile)
    const int tx   = t & 15;            // 0..15 (n sub-tile)

    const float* Ag = x + (size_t)(m0 + lrow) * HDIM + lk4;
    const float* Bg = W + (size_t)(n0 + lrow) * HDIM + lk4;

    float c[8][8];
#pragma unroll
    for (int i = 0; i < 8; i++)
#pragma unroll
        for (int j = 0; j < 8; j++) c[i][j] = 0.0f;

    float4 av = *(const float4*)Ag;
    float4 bw = *(const float4*)Bg;

    for (int k0 = 0; k0 < HDIM; k0 += 8) {
        __syncthreads();
        As[lk4 + 0][lrow] = av.x; As[lk4 + 1][lrow] = av.y;
        As[lk4 + 2][lrow] = av.z; As[lk4 + 3][lrow] = av.w;
        Bs[lk4 + 0][lrow] = bw.x; Bs[lk4 + 1][lrow] = bw.y;
        Bs[lk4 + 2][lrow] = bw.z; Bs[lk4 + 3][lrow] = bw.w;
        __syncthreads();
        if (k0 + 8 < HDIM) {
            av = *(const float4*)(Ag + k0 + 8);
            bw = *(const float4*)(Bg + k0 + 8);
        }
#pragma unroll
        for (int kk = 0; kk < 8; kk++) {
            float a[8], b[8];
#pragma unroll
            for (int i = 0; i < 8; i++) a[i] = As[kk][ty * 8 + i];
#pragma unroll
            for (int j = 0; j < 8; j++) b[j] = Bs[kk][tx * 8 + j];
#pragma unroll
            for (int i = 0; i < 8; i++)
#pragma unroll
                for (int j = 0; j < 8; j++) c[i][j] += a[i] * b[j];
        }
    }

#pragma unroll
    for (int i = 0; i < 8; i++) {
        int m = m0 + ty * 8 + i;
        int s = m >> 2;            // m = s*B + b, B=4
        int b = m & 3;
        float* orow = out + ((size_t)b * SDIM + s) * HDIM + n0 + tx * 8;
#pragma unroll
        for (int j = 0; j < 8; j++) orow[j] = c[i][j] + bias[n0 + tx * 8 + j];
    }
}

// scores[b][q][k] = (Q[b][q] . K[b][k]) / 32 + beta * ssm[b][q][k]
__global__ void __launch_bounds__(256) scores_kernel(
    const float* __restrict__ ssm, const float* __restrict__ beta_p)
{
    const int bz = blockIdx.z;
    const float* A = g_Q + (size_t)bz * SDIM * HDIM;
    const float* B = g_K + (size_t)bz * SDIM * HDIM;

    __shared__ float As[8][132];
    __shared__ float Bs[8][132];

    const int t    = threadIdx.x;
    const int m0   = blockIdx.y * 128;
    const int n0   = blockIdx.x * 128;
    const int lrow = t >> 1;
    const int lk4  = (t & 1) * 4;
    const int ty   = t >> 4;
    const int tx   = t & 15;

    const float* Ag = A + (size_t)(m0 + lrow) * HDIM + lk4;
    const float* Bg = B + (size_t)(n0 + lrow) * HDIM + lk4;

    float c[8][8];
#pragma unroll
    for (int i = 0; i < 8; i++)
#pragma unroll
        for (int j = 0; j < 8; j++) c[i][j] = 0.0f;

    float4 av = *(const float4*)Ag;
    float4 bw = *(const float4*)Bg;

    for (int k0 = 0; k0 < HDIM; k0 += 8) {
        __syncthreads();
        As[lk4 + 0][lrow] = av.x; As[lk4 + 1][lrow] = av.y;
        As[lk4 + 2][lrow] = av.z; As[lk4 + 3][lrow] = av.w;
        Bs[lk4 + 0][lrow] = bw.x; Bs[lk4 + 1][lrow] = bw.y;
        Bs[lk4 + 2][lrow] = bw.z; Bs[lk4 + 3][lrow] = bw.w;
        __syncthreads();
        if (k0 + 8 < HDIM) {
            av = *(const float4*)(Ag + k0 + 8);
            bw = *(const float4*)(Bg + k0 + 8);
        }
#pragma unroll
        for (int kk = 0; kk < 8; kk++) {
            float a[8], b[8];
#pragma unroll
            for (int i = 0; i < 8; i++) a[i] = As[kk][ty * 8 + i];
#pragma unroll
            for (int j = 0; j < 8; j++) b[j] = Bs[kk][tx * 8 + j];
#pragma unroll
            for (int i = 0; i < 8; i++)
#pragma unroll
                for (int j = 0; j < 8; j++) c[i][j] += a[i] * b[j];
        }
    }

    const float beta = *beta_p;
    const float inv_scale = 1.0f / 32.0f;   // 1/sqrt(H)
#pragma unroll
    for (int i = 0; i < 8; i++) {
        int m = m0 + ty * 8 + i;
        const float* srow = ssm + ((size_t)bz * SDIM + m) * SDIM + n0 + tx * 8;
        float* drow = g_SC + ((size_t)bz * SDIM + m) * SDIM + n0 + tx * 8;
#pragma unroll
        for (int j = 0; j < 8; j++)
            drow[j] = c[i][j] * inv_scale + beta * srow[j];
    }
}

// Row softmax over S=2048 elements, one CTA (256 threads) per row, in-place.
__global__ void __launch_bounds__(256) softmax_kernel()
{
    __shared__ float redm[8];
    __shared__ float reds[8];
    __shared__ float bcast[2];

    const int row = blockIdx.x;                 // b*S + q
    float* p = g_SC + (size_t)row * SDIM;
    const int t = threadIdx.x;
    const int lane = t & 31, warp = t >> 5;

    float v[8];
    float m = -3.0e38f;
#pragma unroll
    for (int i = 0; i < 8; i++) { v[i] = p[t + 256 * i]; m = fmaxf(m, v[i]); }
#pragma unroll
    for (int o = 16; o; o >>= 1) m = fmaxf(m, __shfl_xor_sync(0xffffffffu, m, o));
    if (lane == 0) redm[warp] = m;
    __syncthreads();
    if (t == 0) {
        float mm = redm[0];
#pragma unroll
        for (int w = 1; w < 8; w++) mm = fmaxf(mm, redm[w]);
        bcast[0] = mm;
    }
    __syncthreads();
    m = bcast[0];

    float ssum = 0.0f;
#pragma unroll
    for (int i = 0; i < 8; i++) { v[i] = __expf(v[i] - m); ssum += v[i]; }
#pragma unroll
    for (int o = 16; o; o >>= 1) ssum += __shfl_xor_sync(0xffffffffu, ssum, o);
    if (lane == 0) reds[warp] = ssum;
    __syncthreads();
    if (t == 0) {
        float s = reds[0];
#pragma unroll
        for (int w = 1; w < 8; w++) s += reds[w];
        bcast[1] = 1.0f / s;
    }
    __syncthreads();
    const float inv = bcast[1];
#pragma unroll
    for (int i = 0; i < 8; i++) p[t + 256 * i] = v[i] * inv;
}

// out[s=q][b][h] = sum_k attn[b][q][k] * V[b][k][h]     (GEMM-NN)
__global__ void __launch_bounds__(256) av_kernel(float* __restrict__ out)
{
    const int bz = blockIdx.z;
    const float* A  = g_SC + (size_t)bz * SDIM * SDIM;   // [M=S][K=S], K-contig
    const float* Bv = g_V  + (size_t)bz * SDIM * HDIM;   // [K=S][N=H], N-contig

    __shared__ float As[8][132];
    __shared__ float Bs[8][132];

    const int t    = threadIdx.x;
    const int m0   = blockIdx.y * 128;
    const int n0   = blockIdx.x * 128;
    const int lrow = t >> 1;            // A: row (m), 0..127
    const int lk4  = (t & 1) * 4;       // A: k offset
    const int kr   = t >> 5;            // B: k row, 0..7
    const int c4   = (t & 31) * 4;      // B: n offset
    const int ty   = t >> 4;
    const int tx   = t & 15;

    const float* Ag = A  + (size_t)(m0 + lrow) * SDIM + lk4;
    const float* Bg = Bv + (size_t)kr * HDIM + n0 + c4;

    float c[8][8];
#pragma unroll
    for (int i = 0; i < 8; i++)
#pragma unroll
        for (int j = 0; j < 8; j++) c[i][j] = 0.0f;

    float4 av = *(const float4*)Ag;
    float4 bw = *(const float4*)Bg;

    for (int k0 = 0; k0 < SDIM; k0 += 8) {
        __syncthreads();
        As[lk4 + 0][lrow] = av.x; As[lk4 + 1][lrow] = av.y;
        As[lk4 + 2][lrow] = av.z; As[lk4 + 3][lrow] = av.w;
        *(float4*)&Bs[kr][c4] = bw;
        __syncthreads();
        if (k0 + 8 < SDIM) {
            av = *(const float4*)(Ag + k0 + 8);
            bw = *(const float4*)(Bg + (size_t)(k0 + 8) * HDIM);
        }
#pragma unroll
        for (int kk = 0; kk < 8; kk++) {
            float a[8], b[8];
#pragma unroll
            for (int i = 0; i < 8; i++) a[i] = As[kk][ty * 8 + i];
#pragma unroll
            for (int j = 0; j < 8; j++) b[j] = Bs[kk][tx * 8 + j];
#pragma unroll
            for (int i = 0; i < 8; i++)
#pragma unroll
                for (int j = 0; j < 8; j++) c[i][j] += a[i] * b[j];
        }
    }

    // out is [S][B][H]: element (q=m, b=bz, h=n)
#pragma unroll
    for (int i = 0; i < 8; i++) {
        int m = m0 + ty * 8 + i;
        float* orow = out + ((size_t)m * BDIM + bz) * HDIM + n0 + tx * 8;
#pragma unroll
        for (int j = 0; j < 8; j++) orow[j] = c[i][j];
    }
}

extern "C" void kernel_launch(void* const* d_in, const int* in_sizes, int n_in,
                              void* d_out, int out_size)
{
    const float* x    = (const float*)d_in[0];
    const float* ssm  = (const float*)d_in[1];
    const float* Wq   = (const float*)d_in[2];
    const float* bq   = (const float*)d_in[3];
    const float* Wk   = (const float*)d_in[4];
    const float* bk   = (const float*)d_in[5];
    const float* Wv   = (const float*)d_in[6];
    const float* bv   = (const float*)d_in[7];
    const float* beta = (const float*)d_in[8];
    float* out = (float*)d_out;

    dim3 blk(256);
    proj_kernel<<<dim3(HDIM / 128, MPROJ / 128, 3), blk>>>(x, Wq, bq, Wk, bk, Wv, bv);
    scores_kernel<<<dim3(SDIM / 128, SDIM / 128, BDIM), blk>>>(ssm, beta);
    softmax_kernel<<<dim3(BDIM * SDIM), blk>>>();
    av_kernel<<<dim3(HDIM / 128, SDIM / 128, BDIM), blk>>>(out);
}